// round 5
// baseline (speedup 1.0000x reference)
#include <cuda_runtime.h>

// CNODExtmod: controlled neural ODE, persistent per-CTA time loop.
// R5: 512 threads / 16 warps per CTA (4 per SMSP) for latency hiding;
//     register-trimmed role maps (<=128 regs/thread). Scalar FFMA only.

#define NCC      32
#define NC1      33
#define HID      128
#define TT       64
#define NSUB     4
#define ROWS     32
#define NTHREADS 512
#define DTC      0.01f
#define CNS      36
#define XS       128

#define O_Y2 262144
#define O_T  524288
#define O_H  524352

#define FMA4(acc, xv, wt, bofs) {                        \
    acc = fmaf((wt)[(bofs)+0], (xv).x, acc);             \
    acc = fmaf((wt)[(bofs)+1], (xv).y, acc);             \
    acc = fmaf((wt)[(bofs)+2], (xv).z, acc);             \
    acc = fmaf((wt)[(bofs)+3], (xv).w, acc); }

__global__ void __launch_bounds__(NTHREADS, 1)
cnode_kernel(const float* __restrict__ times, const float* __restrict__ Y,
             const float* __restrict__ mask,  const float* __restrict__ A,
             const float* __restrict__ Bvec,
             const float* __restrict__ W1, const float* __restrict__ b1,
             const float* __restrict__ W2, const float* __restrict__ b2,
             const float* __restrict__ W3, const float* __restrict__ b3,
             float* __restrict__ out)
{
    __shared__ __align__(16) float CN0[ROWS * CNS];
    __shared__ __align__(16) float CN1[ROWS * CNS];
    __shared__ __align__(16) float X1 [ROWS * XS];
    __shared__ __align__(16) float X2 [ROWS * XS];
    __shared__ __align__(16) float DC1[ROWS * NCC];
    __shared__ float ysh[ROWS];
    __shared__ float msh[ROWS];

    const int tid  = threadIdx.x;
    const int b0   = blockIdx.x * ROWS;
    const int tid2 = tid & 255;
    const int rh   = tid >> 8;          // row half: 0 or 1

    // ---- role maps ----
    // L1: j over 128 outputs, K-split 2, rows [rh*16, rh*16+16)
    const int j1c = tid2 >> 1;
    const int s1  = tid2 & 1;
    // L2: j over 128 outputs, K-split 4, all 32 rows
    const int j2c = (tid >> 2) & 127;
    const int s4  = tid & 3;
    // L3: j3 over 32 outputs, K-split 8, rows [rh*16, rh*16+16)
    const int j3  = tid2 >> 3;
    const int s3  = tid & 7;
    // A-pass: i over 32 outputs, K-split 2, 4 rows per thread
    const int iA  = (tid >> 1) & 31;
    const int sA  = tid & 1;
    const int rgA = tid >> 6;           // 0..7 -> rows rgA*4..+4
    // o32: one row per 16 threads, K-split 16
    const int rO  = tid >> 4;           // 0..31 : batch row
    const int s16 = tid & 15;

    // ---- weights into registers ----
    float w1r[17];
    #pragma unroll
    for (int i = 0; i < 16; i++) w1r[i] = W1[j1c * NC1 + s1 * 16 + i];
    w1r[16] = s1 ? W1[j1c * NC1 + 32] : 0.0f;
    const float b1j = b1[j1c];

    float w2r[32];
    #pragma unroll
    for (int i = 0; i < 32; i++) w2r[i] = W2[j2c * HID + s4 * 32 + i];
    const float b2j = b2[j2c];

    float w3r[16];   // k = s3*4 + m*32 + q
    #pragma unroll
    for (int m = 0; m < 4; m++)
        #pragma unroll
        for (int q = 0; q < 4; q++)
            w3r[m * 4 + q] = W3[j3 * HID + s3 * 4 + m * 32 + q];
    const float b3j = b3[j3];

    float wAr[16];
    #pragma unroll
    for (int k = 0; k < 16; k++) wAr[k] = A[iA * NCC + sA * 16 + k];
    const float Bi = Bvec[iA];

    float w32r[8];   // k = s16*8 .. +8
    #pragma unroll
    for (int k = 0; k < 8; k++) w32r[k] = W3[NCC * HID + s16 * 8 + k];
    const float b3_32 = b3[NCC];

    // ---- init ----
    for (int idx = tid; idx < ROWS * CNS; idx += NTHREADS) {
        CN0[idx] = 0.0f; CN1[idx] = 0.0f;
    }
    if (blockIdx.x == 0 && tid < TT) out[O_T + tid] = times[tid];

    float y_t = 0.0f, m_t = 0.0f;
    if (tid < ROWS) {
        y_t = Y[(b0 + tid) * TT];
        m_t = mask[(b0 + tid) * TT];
    }
    __syncthreads();

    for (int t = 0; t < TT; t++) {
        for (int sub = 0; sub < NSUB; sub++) {
            // ---------- L1: X1 = relu(W1 @ cn1 + b1), 16 rows/thread ----------
            #pragma unroll 2
            for (int rr = 0; rr < 16; rr++) {
                const int r = rh * 16 + rr;
                const float* cr = CN1 + r * CNS + s1 * 16;
                float acc = 0.0f;
                float4 xv;
                xv = *(const float4*)(cr + 0);  FMA4(acc, xv, w1r, 0);
                xv = *(const float4*)(cr + 4);  FMA4(acc, xv, w1r, 4);
                xv = *(const float4*)(cr + 8);  FMA4(acc, xv, w1r, 8);
                xv = *(const float4*)(cr + 12); FMA4(acc, xv, w1r, 12);
                acc = fmaf(w1r[16], CN1[r * CNS + 32], acc);
                float tot = acc + __shfl_xor_sync(0xffffffffu, acc, 1);
                tot = fmaxf(tot + b1j, 0.0f);
                if (!s1) X1[r * XS + j1c] = tot;
            }
            __syncthreads();

            // ---------- L2: X2 = relu(W2 @ X1 + b2), K-split 4, 32 rows ----------
            #pragma unroll 2
            for (int r = 0; r < ROWS; r++) {
                const float* xr = X1 + r * XS + s4 * 32;
                float acc = 0.0f;
                #pragma unroll
                for (int v = 0; v < 8; v++) {
                    float4 xv = *(const float4*)(xr + v * 4);
                    FMA4(acc, xv, w2r, v * 4);
                }
                acc += __shfl_xor_sync(0xffffffffu, acc, 1);
                acc += __shfl_xor_sync(0xffffffffu, acc, 2);
                if (s4 == 0) X2[r * XS + j2c] = fmaxf(acc + b2j, 0.0f);
            }
            __syncthreads();

            // ---------- phase 3: all derivative reads, no state writes ----------
            // A pass: dcn0[i] = A[i,:] @ cn0 + Bvec[i]*cn1[0], 4 rows/thread
            float dcn0[4];
            #pragma unroll
            for (int q = 0; q < 4; q++) {
                const int r = rgA * 4 + q;
                const float* cr = CN0 + r * CNS + sA * 16;
                float acc = 0.0f;
                #pragma unroll
                for (int v = 0; v < 4; v++) {
                    float4 xv = *(const float4*)(cr + v * 4);
                    FMA4(acc, xv, wAr, v * 4);
                }
                if (sA == 0) acc = fmaf(Bi, CN1[r * CNS], acc);
                dcn0[q] = acc + __shfl_xor_sync(0xffffffffu, acc, 1);
            }

            // o32: dcn1[32] for row rO, K-split 16
            float o32;
            {
                const float* xr = X2 + rO * XS + s16 * 8;
                float acc = 0.0f;
                float4 xv = *(const float4*)(xr);     FMA4(acc, xv, w32r, 0);
                xv = *(const float4*)(xr + 4);        FMA4(acc, xv, w32r, 4);
                acc += __shfl_xor_sync(0xffffffffu, acc, 1);
                acc += __shfl_xor_sync(0xffffffffu, acc, 2);
                acc += __shfl_xor_sync(0xffffffffu, acc, 4);
                acc += __shfl_xor_sync(0xffffffffu, acc, 8);
                o32 = acc + b3_32;
            }

            // L3: dcn1[j3] for 16 rows/thread -> DC1
            #pragma unroll 2
            for (int rr = 0; rr < 16; rr++) {
                const int r = rh * 16 + rr;
                const float* xr = X2 + r * XS;
                float acc = 0.0f;
                #pragma unroll
                for (int m = 0; m < 4; m++) {
                    float4 xv = *(const float4*)(xr + s3 * 4 + m * 32);
                    FMA4(acc, xv, w3r, m * 4);
                }
                acc += __shfl_xor_sync(0xffffffffu, acc, 1);
                acc += __shfl_xor_sync(0xffffffffu, acc, 2);
                acc += __shfl_xor_sync(0xffffffffu, acc, 4);
                if (s3 == 0) DC1[r * NCC + j3] = acc + b3j;
            }
            __syncthreads();

            // ---------- phase 4: Euler update ----------
            if (sA == 0) {
                #pragma unroll
                for (int q = 0; q < 4; q++) {
                    const int r = rgA * 4 + q;
                    CN0[r * CNS + iA] += DTC * dcn0[q];
                }
            }
            #pragma unroll
            for (int u = 0; u < 2; u++) {
                const int idx = tid + u * NTHREADS;   // 0..1023 = r*32 + jj
                const int r = idx >> 5, jj = idx & 31;
                CN1[r * CNS + jj] += DTC * DC1[idx];
            }
            if (s16 == 0) CN1[rO * CNS + 32] += DTC * o32;
            __syncthreads();
        }

        // ---------- observation step ----------
        if (tid < ROWS) {
            const float yp = CN1[tid * CNS];
            out[(b0 + tid) * TT + t]        = yp;
            out[O_Y2 + (b0 + tid) * TT + t] = yp;
            ysh[tid] = y_t;
            msh[tid] = m_t;
        }
        __syncthreads();

        // masked update: cn1 <- [y_t, cn0] where mask==1
        for (int idx = tid; idx < ROWS * NC1; idx += NTHREADS) {
            const int r  = idx / NC1;
            const int jj = idx - r * NC1;
            if (msh[r] != 0.0f) {
                CN1[r * CNS + jj] = (jj == 0) ? ysh[r] : CN0[r * CNS + jj - 1];
            }
        }
        if (tid < ROWS && t + 1 < TT) {
            y_t = Y[(b0 + tid) * TT + t + 1];
            m_t = mask[(b0 + tid) * TT + t + 1];
        }
        __syncthreads();
    }

    for (int idx = tid; idx < ROWS * NCC; idx += NTHREADS) {
        const int r = idx >> 5, i = idx & 31;
        out[O_H + (b0 + r) * NCC + i] = CN0[r * CNS + i];
    }
}

extern "C" void kernel_launch(void* const* d_in, const int* in_sizes, int n_in,
                              void* d_out, int out_size)
{
    const float* times = (const float*)d_in[0];
    const float* Y     = (const float*)d_in[1];
    const float* mask  = (const float*)d_in[2];
    const float* A     = (const float*)d_in[3];
    const float* Bvec  = (const float*)d_in[4];
    const float* W1    = (const float*)d_in[5];
    const float* b1    = (const float*)d_in[6];
    const float* W2    = (const float*)d_in[7];
    const float* b2    = (const float*)d_in[8];
    const float* W3    = (const float*)d_in[9];
    const float* b3    = (const float*)d_in[10];
    float* out = (float*)d_out;

    cnode_kernel<<<128, NTHREADS>>>(times, Y, mask, A, Bvec,
                                    W1, b1, W2, b2, W3, b3, out);
}

// round 6
// speedup vs baseline: 3.3930x; 3.3930x over previous
#include <cuda_runtime.h>

// CNODExtmod: controlled neural ODE, persistent per-CTA time loop.
// R6: 256 threads, 1 CTA/SM, spill-free. j-PAIR register tiling in L1/L2
//     (8 FMA per LDS.128) with bank-interleaved K-splits (conflict-free).

#define NCC      32
#define NC1      33
#define HID      128
#define TT       64
#define NSUB     4
#define ROWS     32
#define NTHREADS 256
#define DTC      0.01f
#define CNS      36
#define XS       128

#define O_Y2 262144
#define O_T  524288
#define O_H  524352

#define FMA4(acc, xv, wt, bofs) {                        \
    acc = fmaf((wt)[(bofs)+0], (xv).x, acc);             \
    acc = fmaf((wt)[(bofs)+1], (xv).y, acc);             \
    acc = fmaf((wt)[(bofs)+2], (xv).z, acc);             \
    acc = fmaf((wt)[(bofs)+3], (xv).w, acc); }

__global__ void __launch_bounds__(NTHREADS, 1)
cnode_kernel(const float* __restrict__ times, const float* __restrict__ Y,
             const float* __restrict__ mask,  const float* __restrict__ A,
             const float* __restrict__ Bvec,
             const float* __restrict__ W1, const float* __restrict__ b1,
             const float* __restrict__ W2, const float* __restrict__ b2,
             const float* __restrict__ W3, const float* __restrict__ b3,
             float* __restrict__ out)
{
    __shared__ __align__(16) float CN0[ROWS * CNS];
    __shared__ __align__(16) float CN1[ROWS * CNS];
    __shared__ __align__(16) float X1 [ROWS * XS];
    __shared__ __align__(16) float X2 [ROWS * XS];
    __shared__ __align__(16) float DC1[ROWS * NCC];
    __shared__ float ysh[ROWS];
    __shared__ float msh[ROWS];

    const int tid = threadIdx.x;
    const int b0  = blockIdx.x * ROWS;

    // ---- role maps (all reduction partners stay inside a warp) ----
    // L1: row-half x j-pair x K-split-2
    const int rh  = tid >> 7;                // 0/1 : rows rh*16..+16
    const int jp1 = (tid >> 1) & 63;         // j-pair (2*jp1, 2*jp1+1)
    const int s1  = tid & 1;                 // K half (16 k each; s1==1 adds k=32)
    // L2: j-pair x K-split-4 (interleaved k = s4*4 + v*16 + q)
    const int jp2 = (tid >> 2) & 63;
    const int s4  = tid & 3;
    // L3: j over 32 x K-split-8 (interleaved k = s3*4 + m*32 + q), all rows
    const int j3  = (tid >> 3) & 31;
    const int s3  = tid & 7;
    // A-pass: i over 32 x K-split-2, 8 rows per thread
    const int iA  = (tid >> 1) & 31;
    const int sA  = tid & 1;
    const int rgA = tid >> 6;                // 0..3 : rows rgA*8..+8
    // o32: row over 32 x K-split-8 (interleaved)
    const int rO  = (tid >> 3) & 31;
    const int s8  = tid & 7;

    // ---- weights into registers ----
    float w1r[2][17];
    #pragma unroll
    for (int jj = 0; jj < 2; jj++) {
        const int j = 2 * jp1 + jj;
        #pragma unroll
        for (int i = 0; i < 16; i++) w1r[jj][i] = W1[j * NC1 + s1 * 16 + i];
        w1r[jj][16] = s1 ? W1[j * NC1 + 32] : 0.0f;
    }
    const float b1a = b1[2 * jp1], b1b = b1[2 * jp1 + 1];

    float w2r[2][32];                        // k = s4*4 + v*16 + q
    #pragma unroll
    for (int jj = 0; jj < 2; jj++) {
        const int j = 2 * jp2 + jj;
        #pragma unroll
        for (int v = 0; v < 8; v++)
            #pragma unroll
            for (int q = 0; q < 4; q++)
                w2r[jj][v * 4 + q] = W2[j * HID + s4 * 4 + v * 16 + q];
    }
    const float b2a = b2[2 * jp2], b2b = b2[2 * jp2 + 1];

    float w3r[16];                           // k = s3*4 + m*32 + q
    #pragma unroll
    for (int m = 0; m < 4; m++)
        #pragma unroll
        for (int q = 0; q < 4; q++)
            w3r[m * 4 + q] = W3[j3 * HID + s3 * 4 + m * 32 + q];
    const float b3j = b3[j3];

    float wAr[16];                           // k = sA*16 .. +16
    #pragma unroll
    for (int k = 0; k < 16; k++) wAr[k] = A[iA * NCC + sA * 16 + k];
    const float Bi = Bvec[iA];

    float w32r[16];                          // k = s8*4 + m*32 + q
    #pragma unroll
    for (int m = 0; m < 4; m++)
        #pragma unroll
        for (int q = 0; q < 4; q++)
            w32r[m * 4 + q] = W3[NCC * HID + s8 * 4 + m * 32 + q];
    const float b3_32 = b3[NCC];

    // ---- init ----
    for (int idx = tid; idx < ROWS * CNS; idx += NTHREADS) {
        CN0[idx] = 0.0f; CN1[idx] = 0.0f;
    }
    if (blockIdx.x == 0 && tid < TT) out[O_T + tid] = times[tid];

    float y_t = 0.0f, m_t = 0.0f;
    if (tid < ROWS) {
        y_t = Y[(b0 + tid) * TT];
        m_t = mask[(b0 + tid) * TT];
    }
    __syncthreads();

    for (int t = 0; t < TT; t++) {
        for (int sub = 0; sub < NSUB; sub++) {
            // ---------- L1: X1 = relu(W1 @ cn1 + b1) ----------
            // 16 rows/thread, 2 j, K-split-2 (+k=32 on s1==1)
            #pragma unroll 2
            for (int rr = 0; rr < 16; rr++) {
                const int r = rh * 16 + rr;
                const float* cr = CN1 + r * CNS + s1 * 16;
                float aA = 0.0f, aB = 0.0f;
                #pragma unroll
                for (int v = 0; v < 4; v++) {
                    float4 xv = *(const float4*)(cr + v * 4);
                    FMA4(aA, xv, w1r[0], v * 4);
                    FMA4(aB, xv, w1r[1], v * 4);
                }
                const float x32 = CN1[r * CNS + 32];
                aA = fmaf(w1r[0][16], x32, aA);
                aB = fmaf(w1r[1][16], x32, aB);
                aA += __shfl_xor_sync(0xffffffffu, aA, 1);
                aB += __shfl_xor_sync(0xffffffffu, aB, 1);
                if (!s1) {
                    float2 o;
                    o.x = fmaxf(aA + b1a, 0.0f);
                    o.y = fmaxf(aB + b1b, 0.0f);
                    *(float2*)(X1 + r * XS + 2 * jp1) = o;
                }
            }
            __syncthreads();

            // ---------- L2: X2 = relu(W2 @ X1 + b2) ----------
            // all 32 rows, 2 j, K-split-4 interleaved (conflict-free)
            #pragma unroll 2
            for (int r = 0; r < ROWS; r++) {
                const float* xr = X1 + r * XS + s4 * 4;
                float aA = 0.0f, aB = 0.0f;
                #pragma unroll
                for (int v = 0; v < 8; v++) {
                    float4 xv = *(const float4*)(xr + v * 16);
                    FMA4(aA, xv, w2r[0], v * 4);
                    FMA4(aB, xv, w2r[1], v * 4);
                }
                aA += __shfl_xor_sync(0xffffffffu, aA, 1);
                aA += __shfl_xor_sync(0xffffffffu, aA, 2);
                aB += __shfl_xor_sync(0xffffffffu, aB, 1);
                aB += __shfl_xor_sync(0xffffffffu, aB, 2);
                if (s4 == 0) {
                    float2 o;
                    o.x = fmaxf(aA + b2a, 0.0f);
                    o.y = fmaxf(aB + b2b, 0.0f);
                    *(float2*)(X2 + r * XS + 2 * jp2) = o;
                }
            }
            __syncthreads();

            // ---------- phase 3: all derivative reads, no state writes ----------
            // A pass: dcn0[i] = A[i,:] @ cn0 + Bvec[i]*cn1[0], 8 rows/thread
            float dcn0[8];
            #pragma unroll
            for (int q = 0; q < 8; q++) {
                const int r = rgA * 8 + q;
                const float* cr = CN0 + r * CNS + sA * 16;
                float acc = 0.0f;
                #pragma unroll
                for (int v = 0; v < 4; v++) {
                    float4 xv = *(const float4*)(cr + v * 4);
                    FMA4(acc, xv, wAr, v * 4);
                }
                if (sA == 0) acc = fmaf(Bi, CN1[r * CNS], acc);
                dcn0[q] = acc + __shfl_xor_sync(0xffffffffu, acc, 1);
            }

            // o32: dcn1[32] for row rO, K-split-8 interleaved
            float o32;
            {
                const float* xr = X2 + rO * XS + s8 * 4;
                float acc = 0.0f;
                #pragma unroll
                for (int m = 0; m < 4; m++) {
                    float4 xv = *(const float4*)(xr + m * 32);
                    FMA4(acc, xv, w32r, m * 4);
                }
                acc += __shfl_xor_sync(0xffffffffu, acc, 1);
                acc += __shfl_xor_sync(0xffffffffu, acc, 2);
                acc += __shfl_xor_sync(0xffffffffu, acc, 4);
                o32 = acc + b3_32;
            }

            // L3: dcn1[j3] for all rows -> DC1, K-split-8 interleaved
            #pragma unroll 2
            for (int r = 0; r < ROWS; r++) {
                const float* xr = X2 + r * XS + s3 * 4;
                float acc = 0.0f;
                #pragma unroll
                for (int m = 0; m < 4; m++) {
                    float4 xv = *(const float4*)(xr + m * 32);
                    FMA4(acc, xv, w3r, m * 4);
                }
                acc += __shfl_xor_sync(0xffffffffu, acc, 1);
                acc += __shfl_xor_sync(0xffffffffu, acc, 2);
                acc += __shfl_xor_sync(0xffffffffu, acc, 4);
                if (s3 == 0) DC1[r * NCC + j3] = acc + b3j;
            }
            __syncthreads();

            // ---------- phase 4: Euler update ----------
            if (sA == 0) {
                #pragma unroll
                for (int q = 0; q < 8; q++) {
                    const int r = rgA * 8 + q;
                    CN0[r * CNS + iA] += DTC * dcn0[q];
                }
            }
            #pragma unroll
            for (int u = 0; u < 4; u++) {
                const int idx = tid + u * NTHREADS;   // 0..1023 = r*32 + jj
                const int r = idx >> 5, jj = idx & 31;
                CN1[r * CNS + jj] += DTC * DC1[idx];
            }
            if (s8 == 0) CN1[rO * CNS + 32] += DTC * o32;
            __syncthreads();
        }

        // ---------- observation step ----------
        if (tid < ROWS) {
            const float yp = CN1[tid * CNS];
            out[(b0 + tid) * TT + t]        = yp;
            out[O_Y2 + (b0 + tid) * TT + t] = yp;
            ysh[tid] = y_t;
            msh[tid] = m_t;
        }
        __syncthreads();

        // masked update: cn1 <- [y_t, cn0] where mask==1
        for (int idx = tid; idx < ROWS * NC1; idx += NTHREADS) {
            const int r  = idx / NC1;
            const int jj = idx - r * NC1;
            if (msh[r] != 0.0f) {
                CN1[r * CNS + jj] = (jj == 0) ? ysh[r] : CN0[r * CNS + jj - 1];
            }
        }
        if (tid < ROWS && t + 1 < TT) {
            y_t = Y[(b0 + tid) * TT + t + 1];
            m_t = mask[(b0 + tid) * TT + t + 1];
        }
        __syncthreads();
    }

    for (int idx = tid; idx < ROWS * NCC; idx += NTHREADS) {
        const int r = idx >> 5, i = idx & 31;
        out[O_H + (b0 + r) * NCC + i] = CN0[r * CNS + i];
    }
}

extern "C" void kernel_launch(void* const* d_in, const int* in_sizes, int n_in,
                              void* d_out, int out_size)
{
    const float* times = (const float*)d_in[0];
    const float* Y     = (const float*)d_in[1];
    const float* mask  = (const float*)d_in[2];
    const float* A     = (const float*)d_in[3];
    const float* Bvec  = (const float*)d_in[4];
    const float* W1    = (const float*)d_in[5];
    const float* b1    = (const float*)d_in[6];
    const float* W2    = (const float*)d_in[7];
    const float* b2    = (const float*)d_in[8];
    const float* W3    = (const float*)d_in[9];
    const float* b3    = (const float*)d_in[10];
    float* out = (float*)d_out;

    cnode_kernel<<<128, NTHREADS>>>(times, Y, mask, A, Bvec,
                                    W1, b1, W2, b2, W3, b3, out);
}

// round 7
// speedup vs baseline: 3.6494x; 1.0755x over previous
#include <cuda_runtime.h>

// CNODExtmod: controlled neural ODE, persistent per-CTA time loop.
// R7: R6 body + 148-CTA batch split (27-28 rows/CTA) -> all SMs active.

#define NCC      32
#define NC1      33
#define HID      128
#define TT       64
#define NSUB     4
#define BATCH    4096
#define NCTA     148
#define MAXR     28
#define NTHREADS 256
#define DTC      0.01f
#define CNS      36
#define XS       128

#define O_Y2 262144
#define O_T  524288
#define O_H  524352

#define FMA4(acc, xv, wt, bofs) {                        \
    acc = fmaf((wt)[(bofs)+0], (xv).x, acc);             \
    acc = fmaf((wt)[(bofs)+1], (xv).y, acc);             \
    acc = fmaf((wt)[(bofs)+2], (xv).z, acc);             \
    acc = fmaf((wt)[(bofs)+3], (xv).w, acc); }

__global__ void __launch_bounds__(NTHREADS, 1)
cnode_kernel(const float* __restrict__ times, const float* __restrict__ Y,
             const float* __restrict__ mask,  const float* __restrict__ A,
             const float* __restrict__ Bvec,
             const float* __restrict__ W1, const float* __restrict__ b1,
             const float* __restrict__ W2, const float* __restrict__ b2,
             const float* __restrict__ W3, const float* __restrict__ b3,
             float* __restrict__ out)
{
    __shared__ __align__(16) float CN0[MAXR * CNS];
    __shared__ __align__(16) float CN1[MAXR * CNS];
    __shared__ __align__(16) float X1 [MAXR * XS];
    __shared__ __align__(16) float X2 [MAXR * XS];
    __shared__ __align__(16) float DC1[MAXR * NCC];
    __shared__ float ysh[MAXR];
    __shared__ float msh[MAXR];

    const int tid = threadIdx.x;
    const int cid = blockIdx.x;
    const int b0  = (BATCH * cid) / NCTA;
    const int nr  = (BATCH * (cid + 1)) / NCTA - b0;   // 27 or 28

    // ---- role maps (all reduction partners stay inside a warp) ----
    const int rh  = tid >> 7;                // 0/1 : row half (half = 14)
    const int jp1 = (tid >> 1) & 63;
    const int s1  = tid & 1;
    const int jp2 = (tid >> 2) & 63;
    const int s4  = tid & 3;
    const int j3  = (tid >> 3) & 31;
    const int s3  = tid & 7;
    const int iA  = (tid >> 1) & 31;
    const int sA  = tid & 1;
    const int rgA = tid >> 6;                // 0..3 : rows rgA*7..+7
    const int rO  = (tid >> 3) & 31;
    const int s8  = tid & 7;

    // ---- weights into registers ----
    float w1r[2][17];
    #pragma unroll
    for (int jj = 0; jj < 2; jj++) {
        const int j = 2 * jp1 + jj;
        #pragma unroll
        for (int i = 0; i < 16; i++) w1r[jj][i] = W1[j * NC1 + s1 * 16 + i];
        w1r[jj][16] = s1 ? W1[j * NC1 + 32] : 0.0f;
    }
    const float b1a = b1[2 * jp1], b1b = b1[2 * jp1 + 1];

    float w2r[2][32];                        // k = s4*4 + v*16 + q
    #pragma unroll
    for (int jj = 0; jj < 2; jj++) {
        const int j = 2 * jp2 + jj;
        #pragma unroll
        for (int v = 0; v < 8; v++)
            #pragma unroll
            for (int q = 0; q < 4; q++)
                w2r[jj][v * 4 + q] = W2[j * HID + s4 * 4 + v * 16 + q];
    }
    const float b2a = b2[2 * jp2], b2b = b2[2 * jp2 + 1];

    float w3r[16];                           // k = s3*4 + m*32 + q
    #pragma unroll
    for (int m = 0; m < 4; m++)
        #pragma unroll
        for (int q = 0; q < 4; q++)
            w3r[m * 4 + q] = W3[j3 * HID + s3 * 4 + m * 32 + q];
    const float b3j = b3[j3];

    float wAr[16];
    #pragma unroll
    for (int k = 0; k < 16; k++) wAr[k] = A[iA * NCC + sA * 16 + k];
    const float Bi = Bvec[iA];

    float w32r[16];                          // k = s8*4 + m*32 + q
    #pragma unroll
    for (int m = 0; m < 4; m++)
        #pragma unroll
        for (int q = 0; q < 4; q++)
            w32r[m * 4 + q] = W3[NCC * HID + s8 * 4 + m * 32 + q];
    const float b3_32 = b3[NCC];

    // ---- init ----
    for (int idx = tid; idx < MAXR * CNS; idx += NTHREADS) {
        CN0[idx] = 0.0f; CN1[idx] = 0.0f;
    }
    if (cid == 0 && tid < TT) out[O_T + tid] = times[tid];

    float y_t = 0.0f, m_t = 0.0f;
    if (tid < nr) {
        y_t = Y[(b0 + tid) * TT];
        m_t = mask[(b0 + tid) * TT];
    }
    __syncthreads();

    for (int t = 0; t < TT; t++) {
        for (int sub = 0; sub < NSUB; sub++) {
            // ---------- L1: X1 = relu(W1 @ cn1 + b1) ----------
            // rows rh*14 .. min(nr, rh*14+14)
            {
                const int rend = (rh == 0) ? 14 : nr;
                #pragma unroll 2
                for (int r = rh * 14; r < rend; r++) {
                    const float* cr = CN1 + r * CNS + s1 * 16;
                    float aA = 0.0f, aB = 0.0f;
                    #pragma unroll
                    for (int v = 0; v < 4; v++) {
                        float4 xv = *(const float4*)(cr + v * 4);
                        FMA4(aA, xv, w1r[0], v * 4);
                        FMA4(aB, xv, w1r[1], v * 4);
                    }
                    const float x32 = CN1[r * CNS + 32];
                    aA = fmaf(w1r[0][16], x32, aA);
                    aB = fmaf(w1r[1][16], x32, aB);
                    aA += __shfl_xor_sync(0xffffffffu, aA, 1);
                    aB += __shfl_xor_sync(0xffffffffu, aB, 1);
                    if (!s1) {
                        float2 o;
                        o.x = fmaxf(aA + b1a, 0.0f);
                        o.y = fmaxf(aB + b1b, 0.0f);
                        *(float2*)(X1 + r * XS + 2 * jp1) = o;
                    }
                }
            }
            __syncthreads();

            // ---------- L2: X2 = relu(W2 @ X1 + b2) ----------
            #pragma unroll 2
            for (int r = 0; r < nr; r++) {
                const float* xr = X1 + r * XS + s4 * 4;
                float aA = 0.0f, aB = 0.0f;
                #pragma unroll
                for (int v = 0; v < 8; v++) {
                    float4 xv = *(const float4*)(xr + v * 16);
                    FMA4(aA, xv, w2r[0], v * 4);
                    FMA4(aB, xv, w2r[1], v * 4);
                }
                aA += __shfl_xor_sync(0xffffffffu, aA, 1);
                aA += __shfl_xor_sync(0xffffffffu, aA, 2);
                aB += __shfl_xor_sync(0xffffffffu, aB, 1);
                aB += __shfl_xor_sync(0xffffffffu, aB, 2);
                if (s4 == 0) {
                    float2 o;
                    o.x = fmaxf(aA + b2a, 0.0f);
                    o.y = fmaxf(aB + b2b, 0.0f);
                    *(float2*)(X2 + r * XS + 2 * jp2) = o;
                }
            }
            __syncthreads();

            // ---------- phase 3: all derivative reads, no state writes ----------
            // A pass: 7 rows/thread
            float dcn0[7];
            #pragma unroll
            for (int q = 0; q < 7; q++) {
                const int r = rgA * 7 + q;
                if (r < nr) {
                    const float* cr = CN0 + r * CNS + sA * 16;
                    float acc = 0.0f;
                    #pragma unroll
                    for (int v = 0; v < 4; v++) {
                        float4 xv = *(const float4*)(cr + v * 4);
                        FMA4(acc, xv, wAr, v * 4);
                    }
                    if (sA == 0) acc = fmaf(Bi, CN1[r * CNS], acc);
                    dcn0[q] = acc + __shfl_xor_sync(0xffffffffu, acc, 1);
                } else {
                    __shfl_xor_sync(0xffffffffu, 0.0f, 1);
                    dcn0[q] = 0.0f;
                }
            }

            // o32: dcn1[32] for row rO
            float o32 = 0.0f;
            {
                const float* xr = X2 + ((rO < nr) ? rO : 0) * XS + s8 * 4;
                float acc = 0.0f;
                #pragma unroll
                for (int m = 0; m < 4; m++) {
                    float4 xv = *(const float4*)(xr + m * 32);
                    FMA4(acc, xv, w32r, m * 4);
                }
                acc += __shfl_xor_sync(0xffffffffu, acc, 1);
                acc += __shfl_xor_sync(0xffffffffu, acc, 2);
                acc += __shfl_xor_sync(0xffffffffu, acc, 4);
                o32 = acc + b3_32;
            }

            // L3: dcn1[j3] for all rows -> DC1
            #pragma unroll 2
            for (int r = 0; r < nr; r++) {
                const float* xr = X2 + r * XS + s3 * 4;
                float acc = 0.0f;
                #pragma unroll
                for (int m = 0; m < 4; m++) {
                    float4 xv = *(const float4*)(xr + m * 32);
                    FMA4(acc, xv, w3r, m * 4);
                }
                acc += __shfl_xor_sync(0xffffffffu, acc, 1);
                acc += __shfl_xor_sync(0xffffffffu, acc, 2);
                acc += __shfl_xor_sync(0xffffffffu, acc, 4);
                if (s3 == 0) DC1[r * NCC + j3] = acc + b3j;
            }
            __syncthreads();

            // ---------- phase 4: Euler update ----------
            if (sA == 0) {
                #pragma unroll
                for (int q = 0; q < 7; q++) {
                    const int r = rgA * 7 + q;
                    if (r < nr) CN0[r * CNS + iA] += DTC * dcn0[q];
                }
            }
            for (int idx = tid; idx < nr * NCC; idx += NTHREADS) {
                const int r = idx >> 5, jj = idx & 31;
                CN1[r * CNS + jj] += DTC * DC1[idx];
            }
            if (s8 == 0 && rO < nr) CN1[rO * CNS + 32] += DTC * o32;
            __syncthreads();
        }

        // ---------- observation step ----------
        if (tid < nr) {
            const float yp = CN1[tid * CNS];
            out[(b0 + tid) * TT + t]        = yp;
            out[O_Y2 + (b0 + tid) * TT + t] = yp;
            ysh[tid] = y_t;
            msh[tid] = m_t;
        }
        __syncthreads();

        // masked update: cn1 <- [y_t, cn0] where mask==1
        for (int idx = tid; idx < nr * NC1; idx += NTHREADS) {
            const int r  = idx / NC1;
            const int jj = idx - r * NC1;
            if (msh[r] != 0.0f) {
                CN1[r * CNS + jj] = (jj == 0) ? ysh[r] : CN0[r * CNS + jj - 1];
            }
        }
        if (tid < nr && t + 1 < TT) {
            y_t = Y[(b0 + tid) * TT + t + 1];
            m_t = mask[(b0 + tid) * TT + t + 1];
        }
        __syncthreads();
    }

    for (int idx = tid; idx < nr * NCC; idx += NTHREADS) {
        const int r = idx >> 5, i = idx & 31;
        out[O_H + (b0 + r) * NCC + i] = CN0[r * CNS + i];
    }
}

extern "C" void kernel_launch(void* const* d_in, const int* in_sizes, int n_in,
                              void* d_out, int out_size)
{
    const float* times = (const float*)d_in[0];
    const float* Y     = (const float*)d_in[1];
    const float* mask  = (const float*)d_in[2];
    const float* A     = (const float*)d_in[3];
    const float* Bvec  = (const float*)d_in[4];
    const float* W1    = (const float*)d_in[5];
    const float* b1    = (const float*)d_in[6];
    const float* W2    = (const float*)d_in[7];
    const float* b2    = (const float*)d_in[8];
    const float* W3    = (const float*)d_in[9];
    const float* b3    = (const float*)d_in[10];
    float* out = (float*)d_out;

    cnode_kernel<<<NCTA, NTHREADS>>>(times, Y, mask, A, Bvec,
                                     W1, b1, W2, b2, W3, b3, out);
}

// round 9
// speedup vs baseline: 11.4234x; 3.1302x over previous
#include <cuda_runtime.h>
#include <cuda_bf16.h>

// CNODExtmod R9: tensor-core path via mma.sync.m16n8k16 bf16 (sm_100-safe,
// no tcgen05). 128 CTAs x 128 threads, M=32 rows/CTA, weights in swizzled
// SMEM, 3-pass hi/lo bf16 with fp32 accumulation.

typedef unsigned int u32;

#define TT    64
#define NSUB  4
#define DTC   0.01f
#define NCTA  128
#define NTH   128

#define O_Y2 262144
#define O_T  524288
#define O_H  524352

// ---- SMEM byte offsets (dynamic) ----
#define SM_UH    0         // U operand  [32 x 64]  bf16 hi, rs=128B
#define SM_UL    4096
#define SM_X1H   8192      // X1 operand [32 x 128] bf16 hi, rs=256B
#define SM_X1L   16384
#define SM_X2H   24576
#define SM_X2L   32768
#define SM_W1AH  40960     // W1A [160 x 64] (n<128: W1 k<32 | n>=128: A at k 32..63)
#define SM_W1AL  61440
#define SM_W2H   81920     // W2 [128 x 128]
#define SM_W2L   114688
#define SM_W3H   147456    // W3ext [40 x 128]
#define SM_W3L   157696
#define SM_CN0   167936    // 32*32 f32
#define SM_CN1   172032    // 32*36 f32 (stride 36)
#define SM_B1    176640    // 128 f32
#define SM_B2    177152
#define SM_B3    177664    // 40 f32 (pad)
#define SM_W1C32 177920    // 128 f32 : W1[:,32]
#define SM_BV    178432    // 32 f32
#define SM_C10   178560    // 32 f32 : cn1[0] staged
#define SM_C132  178688    // 32 f32 : cn1[32] staged
#define SM_TOTAL 178816

// ---------------- helpers ----------------
__device__ __forceinline__ u32 s2u(const void* p) {
    u32 a;
    asm("{ .reg .u64 t; cvta.to.shared.u64 t, %1; cvt.u32.u64 %0, t; }"
        : "=r"(a) : "l"(p));
    return a;
}
// swizzled byte offset: 16B-chunk index XORed with (row & 7). rs in {128,256}.
__device__ __forceinline__ int swoff(int r, int k, int rs) {
    return r * rs + ((((k >> 3) ^ (r & 7)) << 4) | ((k & 7) << 1));
}
__device__ __forceinline__ void ldsm4(u32 a, u32& r0, u32& r1, u32& r2, u32& r3) {
    asm volatile("ldmatrix.sync.aligned.m8n8.x4.shared.b16 {%0,%1,%2,%3},[%4];"
                 : "=r"(r0), "=r"(r1), "=r"(r2), "=r"(r3) : "r"(a));
}
__device__ __forceinline__ void ldsm2(u32 a, u32& r0, u32& r1) {
    asm volatile("ldmatrix.sync.aligned.m8n8.x2.shared.b16 {%0,%1},[%2];"
                 : "=r"(r0), "=r"(r1) : "r"(a));
}
// A-frag (m16k16) for m-tile mt, k-step ks from [row][k] bf16 buffer
__device__ __forceinline__ void ldA(u32 base, int rs, int mt, int ks, int lane, u32* a) {
    const int quad = lane >> 3, i = lane & 7;
    const int row = mt * 16 + ((quad & 1) << 3) + i;
    const int k   = ks * 16 + ((quad >> 1) << 3);
    ldsm4(base + swoff(row, k, rs), a[0], a[1], a[2], a[3]);
}
// B-frag (k16n8) for n-tile at n0, k-step ks from [n][k] bf16 weight buffer
__device__ __forceinline__ void ldB(u32 base, int rs, int n0, int ks, int lane, u32* b) {
    const int l = lane & 15;
    const int row = n0 + (l & 7);
    const int k   = ks * 16 + ((l >> 3) << 3);
    ldsm2(base + swoff(row, k, rs), b[0], b[1]);
}
__device__ __forceinline__ void mma16816(float* d, const u32* a, const u32* b) {
    asm volatile(
        "mma.sync.aligned.m16n8k16.row.col.f32.bf16.bf16.f32 "
        "{%0,%1,%2,%3}, {%4,%5,%6,%7}, {%8,%9}, {%0,%1,%2,%3};"
        : "+f"(d[0]), "+f"(d[1]), "+f"(d[2]), "+f"(d[3])
        : "r"(a[0]), "r"(a[1]), "r"(a[2]), "r"(a[3]), "r"(b[0]), "r"(b[1]));
}
__device__ __forceinline__ void mma3(float* d, const u32* ah, const u32* al,
                                     const u32* bh, const u32* bl) {
    mma16816(d, ah, bh);
    mma16816(d, al, bh);
    mma16816(d, ah, bl);
}
// split pair (va,vb) -> packed bf16 hi and lo residue
__device__ __forceinline__ void hlpair(float va, float vb, u32& ho, u32& lo) {
    __nv_bfloat162 h = __floats2bfloat162_rn(va, vb);
    float ra = va - __low2float(h);
    float rb = vb - __high2float(h);
    __nv_bfloat162 l = __floats2bfloat162_rn(ra, rb);
    ho = *reinterpret_cast<u32*>(&h);
    lo = *reinterpret_cast<u32*>(&l);
}
// store one 8-element chunk (16B hi + 16B lo) at swizzled offset
__device__ __forceinline__ void st_chunk_hl(char* bh, char* bl, int off, const float* v) {
    u32 h[4], l[4];
    #pragma unroll
    for (int p = 0; p < 4; p++) hlpair(v[2 * p], v[2 * p + 1], h[p], l[p]);
    *(uint4*)(bh + off) = make_uint4(h[0], h[1], h[2], h[3]);
    *(uint4*)(bl + off) = make_uint4(l[0], l[1], l[2], l[3]);
}

__global__ void __launch_bounds__(NTH, 1)
cnode_mma_kernel(const float* __restrict__ times, const float* __restrict__ Y,
                 const float* __restrict__ mask,  const float* __restrict__ A,
                 const float* __restrict__ Bvec,
                 const float* __restrict__ W1, const float* __restrict__ b1,
                 const float* __restrict__ W2, const float* __restrict__ b2,
                 const float* __restrict__ W3, const float* __restrict__ b3,
                 float* __restrict__ out)
{
    extern __shared__ __align__(128) char sm[];
    const u32 sb = s2u(sm);
    const int tid  = threadIdx.x;
    const int w    = tid >> 5;
    const int lane = tid & 31;
    const int b0   = blockIdx.x * 32;

    float* CN0S = (float*)(sm + SM_CN0);
    float* CN1S = (float*)(sm + SM_CN1);
    float* B1S  = (float*)(sm + SM_B1);
    float* B2S  = (float*)(sm + SM_B2);
    float* B3S  = (float*)(sm + SM_B3);
    float* W1C  = (float*)(sm + SM_W1C32);
    float* BV   = (float*)(sm + SM_BV);
    float* C10  = (float*)(sm + SM_C10);
    float* C132 = (float*)(sm + SM_C132);

    // ---------------- one-time weight conversion ----------------
    {
        float v[8];
        // W1A [160 x 64]: n<128 -> W1 (k<32) ; n>=128 -> A at k 32..63
        for (int r = tid; r < 160; r += NTH) {
            #pragma unroll
            for (int c8 = 0; c8 < 8; c8++) {
                #pragma unroll
                for (int i = 0; i < 8; i++) {
                    const int k = c8 * 8 + i;
                    float x;
                    if (r < 128) x = (k < 32) ? W1[r * 33 + k] : 0.0f;
                    else         x = (k >= 32) ? A[(r - 128) * 32 + (k - 32)] : 0.0f;
                    v[i] = x;
                }
                const int off = swoff(r, c8 * 8, 128);
                st_chunk_hl(sm + SM_W1AH, sm + SM_W1AL, off, v);
            }
        }
        // W2 [128 x 128]
        {
            const int r = tid;
            #pragma unroll
            for (int c8 = 0; c8 < 16; c8++) {
                #pragma unroll
                for (int i = 0; i < 8; i++) v[i] = W2[r * 128 + c8 * 8 + i];
                const int off = swoff(r, c8 * 8, 256);
                st_chunk_hl(sm + SM_W2H, sm + SM_W2L, off, v);
            }
        }
        // W3ext [40 x 128]
        if (tid < 40) {
            const int r = tid;
            #pragma unroll
            for (int c8 = 0; c8 < 16; c8++) {
                #pragma unroll
                for (int i = 0; i < 8; i++)
                    v[i] = (r < 33) ? W3[r * 128 + c8 * 8 + i] : 0.0f;
                const int off = swoff(r, c8 * 8, 256);
                st_chunk_hl(sm + SM_W3H, sm + SM_W3L, off, v);
            }
        }
        // scalars
        B1S[tid] = b1[tid];
        B2S[tid] = b2[tid];
        W1C[tid] = W1[tid * 33 + 32];
        if (tid < 40) B3S[tid] = (tid < 33) ? b3[tid] : 0.0f;
        if (tid < 32) BV[tid] = Bvec[tid];
        // zero state
        for (int i = tid; i < 32 * 32; i += NTH) CN0S[i] = 0.0f;
        for (int i = tid; i < 32 * 36; i += NTH) CN1S[i] = 0.0f;
    }
    if (blockIdx.x == 0 && tid < TT) out[O_T + tid] = times[tid];

    float y_t = 0.0f, m_t = 0.0f;
    if (tid < 32) {
        y_t = Y[(b0 + tid) * TT];
        m_t = mask[(b0 + tid) * TT];
    }
    __syncthreads();

    const u32 bUH  = sb + SM_UH,  bUL  = sb + SM_UL;
    const u32 bX1H = sb + SM_X1H, bX1L = sb + SM_X1L;
    const u32 bX2H = sb + SM_X2H, bX2L = sb + SM_X2L;
    const u32 bW1H = sb + SM_W1AH, bW1L = sb + SM_W1AL;
    const u32 bW2H = sb + SM_W2H,  bW2L = sb + SM_W2L;
    const u32 bW3H = sb + SM_W3H,  bW3L = sb + SM_W3L;

    for (int t = 0; t < TT; t++) {
        for (int sub = 0; sub < NSUB; sub++) {
            // ---------- U build: U = [cn1[0..31] | cn0[0..31]] hi/lo ----------
            {
                const int r = tid >> 2, q = tid & 3;
                float v[16];
                if (q < 2) {
                    const float* s = CN1S + r * 36 + q * 16;
                    #pragma unroll
                    for (int p = 0; p < 4; p++) {
                        float4 f = *(const float4*)(s + 4 * p);
                        v[4*p] = f.x; v[4*p+1] = f.y; v[4*p+2] = f.z; v[4*p+3] = f.w;
                    }
                } else {
                    const float* s = CN0S + r * 32 + (q - 2) * 16;
                    #pragma unroll
                    for (int p = 0; p < 4; p++) {
                        float4 f = *(const float4*)(s + 4 * p);
                        v[4*p] = f.x; v[4*p+1] = f.y; v[4*p+2] = f.z; v[4*p+3] = f.w;
                    }
                }
                st_chunk_hl(sm + SM_UH, sm + SM_UL, swoff(r, q * 16, 128), v);
                st_chunk_hl(sm + SM_UH, sm + SM_UL, swoff(r, q * 16 + 8, 128), v + 8);
                if (q == 0) {
                    C10[r]  = CN1S[r * 36];
                    C132[r] = CN1S[r * 36 + 32];
                }
            }
            __syncthreads();

            // ---------- GEMM1: [X1 | dcn0] = U @ W1A^T ----------
            float aX[4][2][4] = {};
            float aA[2][4] = {};
            {
                u32 Ah[2][4], Al[2][4], Bh[2], Bl[2];
                #pragma unroll
                for (int ks = 0; ks < 2; ks++) {          // W1 block (cn1 cols)
                    #pragma unroll
                    for (int mt = 0; mt < 2; mt++) {
                        ldA(bUH, 128, mt, ks, lane, Ah[mt]);
                        ldA(bUL, 128, mt, ks, lane, Al[mt]);
                    }
                    #pragma unroll
                    for (int it = 0; it < 4; it++) {
                        const int n0 = (w + it * 4) * 8;
                        ldB(bW1H, 128, n0, ks, lane, Bh);
                        ldB(bW1L, 128, n0, ks, lane, Bl);
                        #pragma unroll
                        for (int mt = 0; mt < 2; mt++)
                            mma3(aX[it][mt], Ah[mt], Al[mt], Bh, Bl);
                    }
                }
                #pragma unroll
                for (int ks = 2; ks < 4; ks++) {          // A block (cn0 cols)
                    #pragma unroll
                    for (int mt = 0; mt < 2; mt++) {
                        ldA(bUH, 128, mt, ks, lane, Ah[mt]);
                        ldA(bUL, 128, mt, ks, lane, Al[mt]);
                    }
                    const int n0 = 128 + w * 8;
                    ldB(bW1H, 128, n0, ks, lane, Bh);
                    ldB(bW1L, 128, n0, ks, lane, Bl);
                    #pragma unroll
                    for (int mt = 0; mt < 2; mt++)
                        mma3(aA[mt], Ah[mt], Al[mt], Bh, Bl);
                }
            }
            // epilogue 1: X1 = relu(d + W1[:,32]*cn1[32] + b1) -> hi/lo SMEM
            #pragma unroll
            for (int it = 0; it < 4; it++) {
                const int c0 = (w + it * 4) * 8 + 2 * (lane & 3);
                const float w1a = W1C[c0], w1b = W1C[c0 + 1];
                const float bb1 = B1S[c0], bb2 = B1S[c0 + 1];
                #pragma unroll
                for (int mt = 0; mt < 2; mt++) {
                    #pragma unroll
                    for (int hh = 0; hh < 2; hh++) {
                        const int r = mt * 16 + (lane >> 2) + hh * 8;
                        const float cx = C132[r];
                        float va = fmaxf(aX[it][mt][hh*2+0] + w1a * cx + bb1, 0.0f);
                        float vb = fmaxf(aX[it][mt][hh*2+1] + w1b * cx + bb2, 0.0f);
                        u32 ho, lo; hlpair(va, vb, ho, lo);
                        const int off = swoff(r, c0, 256);
                        *(u32*)(sm + SM_X1H + off) = ho;
                        *(u32*)(sm + SM_X1L + off) = lo;
                    }
                }
            }
            // epilogue 1b: cn0 += dt * (dcn0 + Bvec*cn1[0])
            {
                const int c0 = w * 8 + 2 * (lane & 3);
                const float bva = BV[c0], bvb = BV[c0 + 1];
                #pragma unroll
                for (int mt = 0; mt < 2; mt++) {
                    #pragma unroll
                    for (int hh = 0; hh < 2; hh++) {
                        const int r = mt * 16 + (lane >> 2) + hh * 8;
                        const float c1v = C10[r];
                        CN0S[r * 32 + c0]     += DTC * (aA[mt][hh*2+0] + bva * c1v);
                        CN0S[r * 32 + c0 + 1] += DTC * (aA[mt][hh*2+1] + bvb * c1v);
                    }
                }
            }
            __syncthreads();

            // ---------- GEMM2: X2 = relu(X1 @ W2^T + b2) ----------
            float a2[4][2][4] = {};
            {
                u32 Ah[2][4], Al[2][4], Bh[2], Bl[2];
                #pragma unroll
                for (int ks = 0; ks < 8; ks++) {
                    #pragma unroll
                    for (int mt = 0; mt < 2; mt++) {
                        ldA(bX1H, 256, mt, ks, lane, Ah[mt]);
                        ldA(bX1L, 256, mt, ks, lane, Al[mt]);
                    }
                    #pragma unroll
                    for (int it = 0; it < 4; it++) {
                        const int n0 = (w + it * 4) * 8;
                        ldB(bW2H, 256, n0, ks, lane, Bh);
                        ldB(bW2L, 256, n0, ks, lane, Bl);
                        #pragma unroll
                        for (int mt = 0; mt < 2; mt++)
                            mma3(a2[it][mt], Ah[mt], Al[mt], Bh, Bl);
                    }
                }
            }
            #pragma unroll
            for (int it = 0; it < 4; it++) {
                const int c0 = (w + it * 4) * 8 + 2 * (lane & 3);
                const float bb1 = B2S[c0], bb2 = B2S[c0 + 1];
                #pragma unroll
                for (int mt = 0; mt < 2; mt++) {
                    #pragma unroll
                    for (int hh = 0; hh < 2; hh++) {
                        const int r = mt * 16 + (lane >> 2) + hh * 8;
                        float va = fmaxf(a2[it][mt][hh*2+0] + bb1, 0.0f);
                        float vb = fmaxf(a2[it][mt][hh*2+1] + bb2, 0.0f);
                        u32 ho, lo; hlpair(va, vb, ho, lo);
                        const int off = swoff(r, c0, 256);
                        *(u32*)(sm + SM_X2H + off) = ho;
                        *(u32*)(sm + SM_X2L + off) = lo;
                    }
                }
            }
            __syncthreads();

            // ---------- GEMM3: dcn1 = X2 @ W3ext^T + b3 ----------
            float a3[2][2][4] = {};
            const int ntn = (w == 0) ? 2 : 1;
            int ntl[2]; ntl[0] = w; ntl[1] = 4;
            {
                u32 Ah[2][4], Al[2][4], Bh[2], Bl[2];
                #pragma unroll
                for (int ks = 0; ks < 8; ks++) {
                    #pragma unroll
                    for (int mt = 0; mt < 2; mt++) {
                        ldA(bX2H, 256, mt, ks, lane, Ah[mt]);
                        ldA(bX2L, 256, mt, ks, lane, Al[mt]);
                    }
                    for (int ii = 0; ii < ntn; ii++) {
                        const int n0 = ntl[ii] * 8;
                        ldB(bW3H, 256, n0, ks, lane, Bh);
                        ldB(bW3L, 256, n0, ks, lane, Bl);
                        #pragma unroll
                        for (int mt = 0; mt < 2; mt++)
                            mma3(a3[ii][mt], Ah[mt], Al[mt], Bh, Bl);
                    }
                }
            }
            for (int ii = 0; ii < ntn; ii++) {
                const int c0 = ntl[ii] * 8 + 2 * (lane & 3);
                #pragma unroll
                for (int mt = 0; mt < 2; mt++) {
                    #pragma unroll
                    for (int hh = 0; hh < 2; hh++) {
                        const int r = mt * 16 + (lane >> 2) + hh * 8;
                        if (c0 <= 32)
                            CN1S[r * 36 + c0]     += DTC * (a3[ii][mt][hh*2+0] + B3S[c0]);
                        if (c0 + 1 <= 32)
                            CN1S[r * 36 + c0 + 1] += DTC * (a3[ii][mt][hh*2+1] + B3S[c0 + 1]);
                    }
                }
            }
            __syncthreads();
        }

        // ---------- observation step ----------
        if (tid < 32) {
            const int r = tid;
            const float yp = CN1S[r * 36];
            out[(b0 + r) * TT + t]        = yp;
            out[O_Y2 + (b0 + r) * TT + t] = yp;
            if (m_t != 0.0f) {
                CN1S[r * 36] = y_t;
                #pragma unroll
                for (int j = 1; j < 33; j++)
                    CN1S[r * 36 + j] = CN0S[r * 32 + j - 1];
            }
            if (t + 1 < TT) {
                y_t = Y[(b0 + r) * TT + t + 1];
                m_t = mask[(b0 + r) * TT + t + 1];
            }
        }
        __syncthreads();
    }

    // final hidden state cn0
    if (tid < 32) {
        const int r = tid;
        #pragma unroll
        for (int p = 0; p < 8; p++) {
            float4 f = *(const float4*)(CN0S + r * 32 + 4 * p);
            *(float4*)(out + O_H + (b0 + r) * 32 + 4 * p) = f;
        }
    }
}

extern "C" void kernel_launch(void* const* d_in, const int* in_sizes, int n_in,
                              void* d_out, int out_size)
{
    const float* times = (const float*)d_in[0];
    const float* Y     = (const float*)d_in[1];
    const float* mask  = (const float*)d_in[2];
    const float* A     = (const float*)d_in[3];
    const float* Bvec  = (const float*)d_in[4];
    const float* W1    = (const float*)d_in[5];
    const float* b1    = (const float*)d_in[6];
    const float* W2    = (const float*)d_in[7];
    const float* b2    = (const float*)d_in[8];
    const float* W3    = (const float*)d_in[9];
    const float* b3    = (const float*)d_in[10];
    float* out = (float*)d_out;

    cudaFuncSetAttribute(cnode_mma_kernel,
                         cudaFuncAttributeMaxDynamicSharedMemorySize, SM_TOTAL);
    cnode_mma_kernel<<<NCTA, NTH, SM_TOTAL>>>(times, Y, mask, A, Bvec,
                                              W1, b1, W2, b2, W3, b3, out);
}

// round 10
// speedup vs baseline: 12.9415x; 1.1329x over previous
#include <cuda_runtime.h>
#include <cuda_bf16.h>

// CNODExtmod R10: mma.sync bf16 tensor-core path, now 256 threads / 8 warps
// per CTA (2 per SMSP) for mma latency hiding. 128 CTAs x M=32 rows.
// 3-pass hi/lo bf16, fp32 accumulate, weights in swizzled SMEM.

typedef unsigned int u32;

#define TT    64
#define NSUB  4
#define DTC   0.01f
#define NCTA  128
#define NTH   256

#define O_Y2 262144
#define O_T  524288
#define O_H  524352

// ---- SMEM byte offsets (dynamic) ----
#define SM_UH    0         // U operand  [32 x 64]  bf16 hi, rs=128B
#define SM_UL    4096
#define SM_X1H   8192      // X1 operand [32 x 128] bf16 hi, rs=256B
#define SM_X1L   16384
#define SM_X2H   24576
#define SM_X2L   32768
#define SM_W1AH  40960     // W1A [160 x 64] (n<128: W1 k<32 | n>=128: A at k 32..63)
#define SM_W1AL  61440
#define SM_W2H   81920     // W2 [128 x 128]
#define SM_W2L   114688
#define SM_W3H   147456    // W3ext [40 x 128]
#define SM_W3L   157696
#define SM_CN0   167936    // 32*32 f32
#define SM_CN1   172032    // 32*36 f32 (stride 36)
#define SM_B1    176640    // 128 f32
#define SM_B2    177152
#define SM_B3    177664    // 40 f32 (pad)
#define SM_W1C32 177920    // 128 f32 : W1[:,32]
#define SM_BV    178432    // 32 f32
#define SM_C10   178560    // 32 f32 : cn1[0] staged
#define SM_C132  178688    // 32 f32 : cn1[32] staged
#define SM_TOTAL 178816

// ---------------- helpers ----------------
__device__ __forceinline__ u32 s2u(const void* p) {
    u32 a;
    asm("{ .reg .u64 t; cvta.to.shared.u64 t, %1; cvt.u32.u64 %0, t; }"
        : "=r"(a) : "l"(p));
    return a;
}
// swizzled byte offset: 16B-chunk index XORed with (row & 7). rs in {128,256}.
__device__ __forceinline__ int swoff(int r, int k, int rs) {
    return r * rs + ((((k >> 3) ^ (r & 7)) << 4) | ((k & 7) << 1));
}
__device__ __forceinline__ void ldsm4(u32 a, u32& r0, u32& r1, u32& r2, u32& r3) {
    asm volatile("ldmatrix.sync.aligned.m8n8.x4.shared.b16 {%0,%1,%2,%3},[%4];"
                 : "=r"(r0), "=r"(r1), "=r"(r2), "=r"(r3) : "r"(a));
}
__device__ __forceinline__ void ldsm2(u32 a, u32& r0, u32& r1) {
    asm volatile("ldmatrix.sync.aligned.m8n8.x2.shared.b16 {%0,%1},[%2];"
                 : "=r"(r0), "=r"(r1) : "r"(a));
}
// A-frag (m16k16) for m-tile mt, k-step ks from [row][k] bf16 buffer
__device__ __forceinline__ void ldA(u32 base, int rs, int mt, int ks, int lane, u32* a) {
    const int quad = lane >> 3, i = lane & 7;
    const int row = mt * 16 + ((quad & 1) << 3) + i;
    const int k   = ks * 16 + ((quad >> 1) << 3);
    ldsm4(base + swoff(row, k, rs), a[0], a[1], a[2], a[3]);
}
// B-frag (k16n8) for n-tile at n0, k-step ks from [n][k] bf16 weight buffer
__device__ __forceinline__ void ldB(u32 base, int rs, int n0, int ks, int lane, u32* b) {
    const int l = lane & 15;
    const int row = n0 + (l & 7);
    const int k   = ks * 16 + ((l >> 3) << 3);
    ldsm2(base + swoff(row, k, rs), b[0], b[1]);
}
__device__ __forceinline__ void mma16816(float* d, const u32* a, const u32* b) {
    asm volatile(
        "mma.sync.aligned.m16n8k16.row.col.f32.bf16.bf16.f32 "
        "{%0,%1,%2,%3}, {%4,%5,%6,%7}, {%8,%9}, {%0,%1,%2,%3};"
        : "+f"(d[0]), "+f"(d[1]), "+f"(d[2]), "+f"(d[3])
        : "r"(a[0]), "r"(a[1]), "r"(a[2]), "r"(a[3]), "r"(b[0]), "r"(b[1]));
}
__device__ __forceinline__ void mma3(float* d, const u32* ah, const u32* al,
                                     const u32* bh, const u32* bl) {
    mma16816(d, ah, bh);
    mma16816(d, al, bh);
    mma16816(d, ah, bl);
}
// split pair (va,vb) -> packed bf16 hi and lo residue
__device__ __forceinline__ void hlpair(float va, float vb, u32& ho, u32& lo) {
    __nv_bfloat162 h = __floats2bfloat162_rn(va, vb);
    float ra = va - __low2float(h);
    float rb = vb - __high2float(h);
    __nv_bfloat162 l = __floats2bfloat162_rn(ra, rb);
    ho = *reinterpret_cast<u32*>(&h);
    lo = *reinterpret_cast<u32*>(&l);
}
// store one 8-element chunk (16B hi + 16B lo) at swizzled offset
__device__ __forceinline__ void st_chunk_hl(char* bh, char* bl, int off, const float* v) {
    u32 h[4], l[4];
    #pragma unroll
    for (int p = 0; p < 4; p++) hlpair(v[2 * p], v[2 * p + 1], h[p], l[p]);
    *(uint4*)(bh + off) = make_uint4(h[0], h[1], h[2], h[3]);
    *(uint4*)(bl + off) = make_uint4(l[0], l[1], l[2], l[3]);
}

__global__ void __launch_bounds__(NTH, 1)
cnode_mma_kernel(const float* __restrict__ times, const float* __restrict__ Y,
                 const float* __restrict__ mask,  const float* __restrict__ A,
                 const float* __restrict__ Bvec,
                 const float* __restrict__ W1, const float* __restrict__ b1,
                 const float* __restrict__ W2, const float* __restrict__ b2,
                 const float* __restrict__ W3, const float* __restrict__ b3,
                 float* __restrict__ out)
{
    extern __shared__ __align__(128) char sm[];
    const u32 sb = s2u(sm);
    const int tid  = threadIdx.x;
    const int w    = tid >> 5;      // 0..7
    const int lane = tid & 31;
    const int b0   = blockIdx.x * 32;

    float* CN0S = (float*)(sm + SM_CN0);
    float* CN1S = (float*)(sm + SM_CN1);
    float* B1S  = (float*)(sm + SM_B1);
    float* B2S  = (float*)(sm + SM_B2);
    float* B3S  = (float*)(sm + SM_B3);
    float* W1C  = (float*)(sm + SM_W1C32);
    float* BV   = (float*)(sm + SM_BV);
    float* C10  = (float*)(sm + SM_C10);
    float* C132 = (float*)(sm + SM_C132);

    // ---------------- one-time weight conversion ----------------
    {
        float v[8];
        // W1A [160 x 64]: n<128 -> W1 (k<32) ; n>=128 -> A at k 32..63
        for (int r = tid; r < 160; r += NTH) {
            #pragma unroll
            for (int c8 = 0; c8 < 8; c8++) {
                #pragma unroll
                for (int i = 0; i < 8; i++) {
                    const int k = c8 * 8 + i;
                    float x;
                    if (r < 128) x = (k < 32) ? W1[r * 33 + k] : 0.0f;
                    else         x = (k >= 32) ? A[(r - 128) * 32 + (k - 32)] : 0.0f;
                    v[i] = x;
                }
                const int off = swoff(r, c8 * 8, 128);
                st_chunk_hl(sm + SM_W1AH, sm + SM_W1AL, off, v);
            }
        }
        // W2 [128 x 128] : 256 threads, each does half a row
        {
            const int r = tid >> 1, hh = tid & 1;
            #pragma unroll
            for (int c8 = hh * 8; c8 < hh * 8 + 8; c8++) {
                #pragma unroll
                for (int i = 0; i < 8; i++) v[i] = W2[r * 128 + c8 * 8 + i];
                const int off = swoff(r, c8 * 8, 256);
                st_chunk_hl(sm + SM_W2H, sm + SM_W2L, off, v);
            }
        }
        // W3ext [40 x 128]
        if (tid < 80) {
            const int r = tid >> 1, hh = tid & 1;
            #pragma unroll
            for (int c8 = hh * 8; c8 < hh * 8 + 8; c8++) {
                #pragma unroll
                for (int i = 0; i < 8; i++)
                    v[i] = (r < 33) ? W3[r * 128 + c8 * 8 + i] : 0.0f;
                const int off = swoff(r, c8 * 8, 256);
                st_chunk_hl(sm + SM_W3H, sm + SM_W3L, off, v);
            }
        }
        // scalars
        if (tid < 128) {
            B1S[tid] = b1[tid];
            B2S[tid] = b2[tid];
            W1C[tid] = W1[tid * 33 + 32];
        }
        if (tid < 40) B3S[tid] = (tid < 33) ? b3[tid] : 0.0f;
        if (tid < 32) BV[tid] = Bvec[tid];
        // zero state
        for (int i = tid; i < 32 * 32; i += NTH) CN0S[i] = 0.0f;
        for (int i = tid; i < 32 * 36; i += NTH) CN1S[i] = 0.0f;
    }
    if (blockIdx.x == 0 && tid < TT) out[O_T + tid] = times[tid];

    float y_t = 0.0f, m_t = 0.0f;
    if (tid < 32) {
        y_t = Y[(b0 + tid) * TT];
        m_t = mask[(b0 + tid) * TT];
    }
    __syncthreads();

    const u32 bUH  = sb + SM_UH,  bUL  = sb + SM_UL;
    const u32 bX1H = sb + SM_X1H, bX1L = sb + SM_X1L;
    const u32 bX2H = sb + SM_X2H, bX2L = sb + SM_X2L;
    const u32 bW1H = sb + SM_W1AH, bW1L = sb + SM_W1AL;
    const u32 bW2H = sb + SM_W2H,  bW2L = sb + SM_W2L;
    const u32 bW3H = sb + SM_W3H,  bW3L = sb + SM_W3L;

    for (int t = 0; t < TT; t++) {
        for (int sub = 0; sub < NSUB; sub++) {
            // ---------- U build: U = [cn1[0..31] | cn0[0..31]] hi/lo ----------
            // 256 threads: r = tid>>3 (row), c8 = tid&7 (8-col chunk)
            {
                const int r = tid >> 3, c8 = tid & 7;
                float v[8];
                const float* s = (c8 < 4) ? (CN1S + r * 36 + c8 * 8)
                                          : (CN0S + r * 32 + (c8 - 4) * 8);
                float4 f0 = *(const float4*)(s);
                float4 f1 = *(const float4*)(s + 4);
                v[0]=f0.x; v[1]=f0.y; v[2]=f0.z; v[3]=f0.w;
                v[4]=f1.x; v[5]=f1.y; v[6]=f1.z; v[7]=f1.w;
                st_chunk_hl(sm + SM_UH, sm + SM_UL, swoff(r, c8 * 8, 128), v);
                if (c8 == 0) {
                    C10[r]  = CN1S[r * 36];
                    C132[r] = CN1S[r * 36 + 32];
                }
            }
            __syncthreads();

            // ---------- GEMM1: [X1 | dcn0] = U @ W1A^T ----------
            // warp w owns X1 n-tiles {w, w+8}; warps 0-3 also own A-tile 16+w
            float aX[2][2][4] = {};
            float aA[2][4] = {};
            {
                u32 Ah[2][4], Al[2][4], Bh[2], Bl[2];
                #pragma unroll
                for (int ks = 0; ks < 2; ks++) {          // W1 block (cn1 cols)
                    #pragma unroll
                    for (int mt = 0; mt < 2; mt++) {
                        ldA(bUH, 128, mt, ks, lane, Ah[mt]);
                        ldA(bUL, 128, mt, ks, lane, Al[mt]);
                    }
                    #pragma unroll
                    for (int it = 0; it < 2; it++) {
                        const int n0 = (w + it * 8) * 8;
                        ldB(bW1H, 128, n0, ks, lane, Bh);
                        ldB(bW1L, 128, n0, ks, lane, Bl);
                        #pragma unroll
                        for (int mt = 0; mt < 2; mt++)
                            mma3(aX[it][mt], Ah[mt], Al[mt], Bh, Bl);
                    }
                }
                if (w < 4) {
                    #pragma unroll
                    for (int ks = 2; ks < 4; ks++) {      // A block (cn0 cols)
                        #pragma unroll
                        for (int mt = 0; mt < 2; mt++) {
                            ldA(bUH, 128, mt, ks, lane, Ah[mt]);
                            ldA(bUL, 128, mt, ks, lane, Al[mt]);
                        }
                        const int n0 = 128 + w * 8;
                        ldB(bW1H, 128, n0, ks, lane, Bh);
                        ldB(bW1L, 128, n0, ks, lane, Bl);
                        #pragma unroll
                        for (int mt = 0; mt < 2; mt++)
                            mma3(aA[mt], Ah[mt], Al[mt], Bh, Bl);
                    }
                }
            }
            // epilogue 1: X1 = relu(d + W1[:,32]*cn1[32] + b1) -> hi/lo SMEM
            #pragma unroll
            for (int it = 0; it < 2; it++) {
                const int c0 = (w + it * 8) * 8 + 2 * (lane & 3);
                const float w1a = W1C[c0], w1b = W1C[c0 + 1];
                const float bb1 = B1S[c0], bb2 = B1S[c0 + 1];
                #pragma unroll
                for (int mt = 0; mt < 2; mt++) {
                    #pragma unroll
                    for (int hh = 0; hh < 2; hh++) {
                        const int r = mt * 16 + (lane >> 2) + hh * 8;
                        const float cx = C132[r];
                        float va = fmaxf(aX[it][mt][hh*2+0] + w1a * cx + bb1, 0.0f);
                        float vb = fmaxf(aX[it][mt][hh*2+1] + w1b * cx + bb2, 0.0f);
                        u32 ho, lo; hlpair(va, vb, ho, lo);
                        const int off = swoff(r, c0, 256);
                        *(u32*)(sm + SM_X1H + off) = ho;
                        *(u32*)(sm + SM_X1L + off) = lo;
                    }
                }
            }
            // epilogue 1b: cn0 += dt * (dcn0 + Bvec*cn1[0])   (warps 0-3)
            if (w < 4) {
                const int c0 = w * 8 + 2 * (lane & 3);
                const float bva = BV[c0], bvb = BV[c0 + 1];
                #pragma unroll
                for (int mt = 0; mt < 2; mt++) {
                    #pragma unroll
                    for (int hh = 0; hh < 2; hh++) {
                        const int r = mt * 16 + (lane >> 2) + hh * 8;
                        const float c1v = C10[r];
                        CN0S[r * 32 + c0]     += DTC * (aA[mt][hh*2+0] + bva * c1v);
                        CN0S[r * 32 + c0 + 1] += DTC * (aA[mt][hh*2+1] + bvb * c1v);
                    }
                }
            }
            __syncthreads();

            // ---------- GEMM2: X2 = relu(X1 @ W2^T + b2) ----------
            float a2[2][2][4] = {};
            {
                u32 Ah[2][4], Al[2][4], Bh[2], Bl[2];
                #pragma unroll
                for (int ks = 0; ks < 8; ks++) {
                    #pragma unroll
                    for (int mt = 0; mt < 2; mt++) {
                        ldA(bX1H, 256, mt, ks, lane, Ah[mt]);
                        ldA(bX1L, 256, mt, ks, lane, Al[mt]);
                    }
                    #pragma unroll
                    for (int it = 0; it < 2; it++) {
                        const int n0 = (w + it * 8) * 8;
                        ldB(bW2H, 256, n0, ks, lane, Bh);
                        ldB(bW2L, 256, n0, ks, lane, Bl);
                        #pragma unroll
                        for (int mt = 0; mt < 2; mt++)
                            mma3(a2[it][mt], Ah[mt], Al[mt], Bh, Bl);
                    }
                }
            }
            #pragma unroll
            for (int it = 0; it < 2; it++) {
                const int c0 = (w + it * 8) * 8 + 2 * (lane & 3);
                const float bb1 = B2S[c0], bb2 = B2S[c0 + 1];
                #pragma unroll
                for (int mt = 0; mt < 2; mt++) {
                    #pragma unroll
                    for (int hh = 0; hh < 2; hh++) {
                        const int r = mt * 16 + (lane >> 2) + hh * 8;
                        float va = fmaxf(a2[it][mt][hh*2+0] + bb1, 0.0f);
                        float vb = fmaxf(a2[it][mt][hh*2+1] + bb2, 0.0f);
                        u32 ho, lo; hlpair(va, vb, ho, lo);
                        const int off = swoff(r, c0, 256);
                        *(u32*)(sm + SM_X2H + off) = ho;
                        *(u32*)(sm + SM_X2L + off) = lo;
                    }
                }
            }
            __syncthreads();

            // ---------- GEMM3: dcn1 = X2 @ W3ext^T + b3  (warps 0-4) ----------
            float a3[2][4] = {};
            if (w < 5) {
                u32 Ah[2][4], Al[2][4], Bh[2], Bl[2];
                #pragma unroll
                for (int ks = 0; ks < 8; ks++) {
                    #pragma unroll
                    for (int mt = 0; mt < 2; mt++) {
                        ldA(bX2H, 256, mt, ks, lane, Ah[mt]);
                        ldA(bX2L, 256, mt, ks, lane, Al[mt]);
                    }
                    const int n0 = w * 8;
                    ldB(bW3H, 256, n0, ks, lane, Bh);
                    ldB(bW3L, 256, n0, ks, lane, Bl);
                    #pragma unroll
                    for (int mt = 0; mt < 2; mt++)
                        mma3(a3[mt], Ah[mt], Al[mt], Bh, Bl);
                }
                const int c0 = w * 8 + 2 * (lane & 3);
                #pragma unroll
                for (int mt = 0; mt < 2; mt++) {
                    #pragma unroll
                    for (int hh = 0; hh < 2; hh++) {
                        const int r = mt * 16 + (lane >> 2) + hh * 8;
                        if (c0 <= 32)
                            CN1S[r * 36 + c0]     += DTC * (a3[mt][hh*2+0] + B3S[c0]);
                        if (c0 + 1 <= 32)
                            CN1S[r * 36 + c0 + 1] += DTC * (a3[mt][hh*2+1] + B3S[c0 + 1]);
                    }
                }
            }
            __syncthreads();
        }

        // ---------- observation step ----------
        if (tid < 32) {
            const int r = tid;
            const float yp = CN1S[r * 36];
            out[(b0 + r) * TT + t]        = yp;
            out[O_Y2 + (b0 + r) * TT + t] = yp;
            if (m_t != 0.0f) {
                CN1S[r * 36] = y_t;
                #pragma unroll
                for (int j = 1; j < 33; j++)
                    CN1S[r * 36 + j] = CN0S[r * 32 + j - 1];
            }
            if (t + 1 < TT) {
                y_t = Y[(b0 + r) * TT + t + 1];
                m_t = mask[(b0 + r) * TT + t + 1];
            }
        }
        __syncthreads();
    }

    // final hidden state cn0
    if (tid < 32) {
        const int r = tid;
        #pragma unroll
        for (int p = 0; p < 8; p++) {
            float4 f = *(const float4*)(CN0S + r * 32 + 4 * p);
            *(float4*)(out + O_H + (b0 + r) * 32 + 4 * p) = f;
        }
    }
}

extern "C" void kernel_launch(void* const* d_in, const int* in_sizes, int n_in,
                              void* d_out, int out_size)
{
    const float* times = (const float*)d_in[0];
    const float* Y     = (const float*)d_in[1];
    const float* mask  = (const float*)d_in[2];
    const float* A     = (const float*)d_in[3];
    const float* Bvec  = (const float*)d_in[4];
    const float* W1    = (const float*)d_in[5];
    const float* b1    = (const float*)d_in[6];
    const float* W2    = (const float*)d_in[7];
    const float* b2    = (const float*)d_in[8];
    const float* W3    = (const float*)d_in[9];
    const float* b3    = (const float*)d_in[10];
    float* out = (float*)d_out;

    cudaFuncSetAttribute(cnode_mma_kernel,
                         cudaFuncAttributeMaxDynamicSharedMemorySize, SM_TOTAL);
    cnode_mma_kernel<<<NCTA, NTH, SM_TOTAL>>>(times, Y, mask, A, Bvec,
                                              W1, b1, W2, b2, W3, b3, out);
}